// round 4
// baseline (speedup 1.0000x reference)
#include <cuda_runtime.h>
#include <cstdint>

#define DEV_INLINE __device__ __forceinline__

// Problem shape (fixed)
static constexpr int Bb = 256, Tt = 256, Ii = 2048, Hh = 128;
static constexpr int Mtot = Bb * Tt;      // 65536 rows of xp
static constexpr int MT   = 256;          // M rows per CTA
static constexpr int NT   = 128;          // N (= full H)
static constexpr int KT   = 32;           // K per tile (32 floats = 128B rows)
static constexpr int NKT  = Ii / KT;      // 64 K tiles
static constexpr int STAGES = 4;
static constexpr int A_BYTES = MT * 128;          // 32 KB
static constexpr int B_BYTES = NT * 128;          // 16 KB
static constexpr int STAGE_BYTES = A_BYTES + B_BYTES;   // 48 KB
static constexpr int SMEM_TOTAL = STAGES * STAGE_BYTES + 1024;

// Scratch: xp[m][h] (32 MB) written by GEMM, read by recurrence
__device__ float g_xp[(size_t)Mtot * Hh];

// ---------------- helpers ----------------
DEV_INLINE uint32_t smem_u32(const void* p) {
    uint32_t a;
    asm("{ .reg .u64 t; cvta.to.shared.u64 t, %1; cvt.u32.u64 %0, t; }" : "=r"(a) : "l"(p));
    return a;
}
DEV_INLINE void cp16(uint32_t saddr, const void* gaddr) {
    asm volatile("cp.async.cg.shared.global [%0], [%1], 16;" :: "r"(saddr), "l"(gaddr));
}
DEV_INLINE void cp_commit() { asm volatile("cp.async.commit_group;" ::: "memory"); }
DEV_INLINE void cp_wait2()  { asm volatile("cp.async.wait_group 2;" ::: "memory"); }

DEV_INLINE void ldsm_x4(uint32_t& r0, uint32_t& r1, uint32_t& r2, uint32_t& r3, uint32_t a) {
    asm volatile("ldmatrix.sync.aligned.m8n8.x4.shared.b16 {%0,%1,%2,%3}, [%4];"
                 : "=r"(r0), "=r"(r1), "=r"(r2), "=r"(r3) : "r"(a));
}
DEV_INLINE void ldsm_x2(uint32_t& r0, uint32_t& r1, uint32_t a) {
    asm volatile("ldmatrix.sync.aligned.m8n8.x2.shared.b16 {%0,%1}, [%2];"
                 : "=r"(r0), "=r"(r1) : "r"(a));
}
DEV_INLINE uint32_t rna_tf32(uint32_t v) {  // round-to-nearest tf32 on fp32 bits
    uint32_t r;
    asm("cvt.rna.tf32.f32 %0, %1;" : "=r"(r) : "f"(__uint_as_float(v)));
    return r;
}
DEV_INLINE void mma_tf32(float* c, uint32_t a0, uint32_t a1, uint32_t a2, uint32_t a3,
                         uint32_t b0, uint32_t b1) {
    asm volatile("mma.sync.aligned.m16n8k8.row.col.f32.tf32.tf32.f32 "
                 "{%0,%1,%2,%3}, {%4,%5,%6,%7}, {%8,%9}, {%0,%1,%2,%3};"
                 : "+f"(c[0]), "+f"(c[1]), "+f"(c[2]), "+f"(c[3])
                 : "r"(a0), "r"(a1), "r"(a2), "r"(a3), "r"(b0), "r"(b1));
}

// ---------------- Kernel A: xp = x @ W_ih^T + (b_ih+b_hh) ----------------
// CTA: 256x128 tile, 8 warps (4 M x 2 N), warp tile 64x64, tf32 mma.sync.
__global__ void __launch_bounds__(256, 1) xp_gemm(
    const float* __restrict__ x, const float* __restrict__ Wih,
    const float* __restrict__ bih, const float* __restrict__ bhh)
{
    extern __shared__ char dsm[];
    __shared__ float s_bias[NT];

    const int tid = threadIdx.x;
    const int wid = tid >> 5, lane = tid & 31;
    const int warp_m = wid >> 1, warp_n = wid & 1;        // 4 x 2
    const int g = lane >> 2, tig = lane & 3;              // mma group / thread-in-group
    const uint32_t base = (smem_u32(dsm) + 1023u) & ~1023u;
    const int m_base = blockIdx.x * MT;

    if (tid < NT) s_bias[tid] = bih[tid] + bhh[tid];

    // per-thread cp.async mapping: idx = i*256 + tid -> row = idx>>3, chunk = idx&7
    const int cp_c = tid & 7;                 // chunk 0..7 (16B each)
    const int cp_r = tid >> 3;                // base row, step 32

    auto issue_stage = [&](int kc, int s) {
        const uint32_t sA = base + s * STAGE_BYTES;
        const uint32_t sB = sA + A_BYTES;
        const float* gA = x + (size_t)(m_base + cp_r) * Ii + kc * KT + cp_c * 4;
        #pragma unroll
        for (int i = 0; i < 8; i++) {
            int row = cp_r + i * 32;
            uint32_t off = row * 128 + ((cp_c ^ (row & 7)) << 4);
            cp16(sA + off, gA + (size_t)i * 32 * Ii);
        }
        const float* gB = Wih + (size_t)cp_r * Ii + kc * KT + cp_c * 4;
        #pragma unroll
        for (int i = 0; i < 4; i++) {
            int row = cp_r + i * 32;
            uint32_t off = row * 128 + ((cp_c ^ (row & 7)) << 4);
            cp16(sB + off, gB + (size_t)i * 32 * Ii);
        }
    };

    // prologue: stages 0..2
    #pragma unroll
    for (int s = 0; s < STAGES - 1; s++) { issue_stage(s, s); cp_commit(); }

    // ldmatrix per-thread address components
    // A: lane l -> matrix ai = l>>3, row-in-matrix aj = l&7
    const int aj = lane & 7, ai = lane >> 3;
    const int a_rowb = warp_m * 64 + (ai & 1) * 8 + aj;   // + ma*16
    const int a_ihi = ai >> 1;                            // k-chunk low bit
    // B: lanes 0..15 supply addresses (x2)
    const int bl = lane & 15;
    const int bj = bl & 7, bi2 = bl >> 3;
    const int b_rowb = warp_n * 64 + bj;                  // + na*8

    float acc[4][8][4];
    #pragma unroll
    for (int ma = 0; ma < 4; ma++)
        #pragma unroll
        for (int na = 0; na < 8; na++)
            #pragma unroll
            for (int q = 0; q < 4; q++) acc[ma][na][q] = 0.0f;

    for (int kc = 0; kc < NKT; kc++) {
        cp_wait2();
        __syncthreads();     // all warps done reading stage (kc-1)&3; stage kc visible
        if (kc + STAGES - 1 < NKT) issue_stage(kc + STAGES - 1, (kc + STAGES - 1) & 3);
        cp_commit();

        const uint32_t sA = base + (kc & 3) * STAGE_BYTES;
        const uint32_t sB = sA + A_BYTES;
        const uint32_t aAbase = sA + a_rowb * 128;
        const uint32_t aBbase = sB + b_rowb * 128;

        #pragma unroll
        for (int ks = 0; ks < 4; ks++) {
            const uint32_t swzA  = (((ks * 2 + a_ihi) ^ (a_rowb & 7)) << 4);
            const uint32_t swzB0 = (((ks * 2 + bi2)  ^ (b_rowb & 7)) << 4);
            uint32_t a[4][4], b[8][2];
            #pragma unroll
            for (int ma = 0; ma < 4; ma++)
                ldsm_x4(a[ma][0], a[ma][1], a[ma][2], a[ma][3], aAbase + ma * 2048 + swzA);
            #pragma unroll
            for (int na = 0; na < 8; na++)
                ldsm_x2(b[na][0], b[na][1], aBbase + na * 1024 + swzB0);
            #pragma unroll
            for (int ma = 0; ma < 4; ma++)
                #pragma unroll
                for (int q = 0; q < 4; q++) a[ma][q] = rna_tf32(a[ma][q]);
            #pragma unroll
            for (int na = 0; na < 8; na++) {
                b[na][0] = rna_tf32(b[na][0]);
                b[na][1] = rna_tf32(b[na][1]);
            }
            #pragma unroll
            for (int ma = 0; ma < 4; ma++)
                #pragma unroll
                for (int na = 0; na < 8; na++)
                    mma_tf32(acc[ma][na], a[ma][0], a[ma][1], a[ma][2], a[ma][3],
                             b[na][0], b[na][1]);
        }
        // no trailing barrier: next iteration's top sync (after cp_wait2) provides
        // the read-before-overwrite guarantee for the 4-deep stage ring.
    }

    // epilogue: + bias -> g_xp (float2 stores, C-fragment layout)
    const int n0 = warp_n * 64 + tig * 2;
    float2 biasv[8];
    #pragma unroll
    for (int na = 0; na < 8; na++) {
        biasv[na].x = s_bias[n0 + na * 8];
        biasv[na].y = s_bias[n0 + na * 8 + 1];
    }
    const int r0 = m_base + warp_m * 64 + g;
    #pragma unroll
    for (int ma = 0; ma < 4; ma++) {
        float* p0 = g_xp + (size_t)(r0 + ma * 16) * Hh;
        float* p1 = p0 + (size_t)8 * Hh;
        #pragma unroll
        for (int na = 0; na < 8; na++) {
            int col = n0 + na * 8;
            float2 v0 = make_float2(acc[ma][na][0] + biasv[na].x, acc[ma][na][1] + biasv[na].y);
            float2 v1 = make_float2(acc[ma][na][2] + biasv[na].x, acc[ma][na][3] + biasv[na].y);
            *reinterpret_cast<float2*>(p0 + col) = v0;
            *reinterpret_cast<float2*>(p1 + col) = v1;
        }
    }
}

// ---------------- Kernel B: 256 sequential tanh-RNN steps + final FC ----------------
// One CTA per batch row; W_hh row j register-resident in thread j; h double-buffered.
__global__ void __launch_bounds__(128, 2) rnn_tail(
    const float* __restrict__ Whh, const float* __restrict__ Wfc,
    const float* __restrict__ bfc, float* __restrict__ out)
{
    __shared__ __align__(16) float hbuf[2][128];
    __shared__ float red[4];
    const int j = threadIdx.x;
    const int b = blockIdx.x;

    float4 w[32];
    #pragma unroll
    for (int i = 0; i < 32; i++)
        w[i] = *reinterpret_cast<const float4*>(Whh + (size_t)j * Hh + i * 4);
    const float wfc = Wfc[j];
    hbuf[0][j] = 0.0f;
    __syncthreads();

    const float* xrow = g_xp + ((size_t)b * Tt) * Hh + j;
    float xv = xrow[0];

    for (int t = 0; t < Tt; t++) {
        float xn = (t + 1 < Tt) ? xrow[(size_t)(t + 1) * Hh] : 0.0f;
        const float* hb = hbuf[t & 1];
        float a0 = xv, a1 = 0.0f, a2 = 0.0f, a3 = 0.0f;
        #pragma unroll
        for (int k = 0; k < 32; k++) {
            float4 hv = *reinterpret_cast<const float4*>(hb + 4 * k);
            a0 = fmaf(hv.x, w[k].x, a0);
            a1 = fmaf(hv.y, w[k].y, a1);
            a2 = fmaf(hv.z, w[k].z, a2);
            a3 = fmaf(hv.w, w[k].w, a3);
        }
        float a = (a0 + a1) + (a2 + a3);
        float u  = __expf(2.0f * a);
        float hn = 1.0f - __fdividef(2.0f, u + 1.0f);
        hbuf[(t + 1) & 1][j] = hn;
        xv = xn;
        __syncthreads();
    }

    float v = wfc * hbuf[0][j];
    #pragma unroll
    for (int o = 16; o > 0; o >>= 1) v += __shfl_down_sync(0xFFFFFFFFu, v, o);
    if ((j & 31) == 0) red[j >> 5] = v;
    __syncthreads();
    if (j == 0) out[b] = red[0] + red[1] + red[2] + red[3] + bfc[0];
}

// ---------------- launch ----------------
extern "C" void kernel_launch(void* const* d_in, const int* in_sizes, int n_in,
                              void* d_out, int out_size)
{
    const float* x   = (const float*)d_in[0];
    const float* Wih = (const float*)d_in[1];
    const float* Whh = (const float*)d_in[2];
    const float* bih = (const float*)d_in[3];
    const float* bhh = (const float*)d_in[4];
    const float* Wfc = (const float*)d_in[5];
    const float* bfc = (const float*)d_in[6];
    float* out = (float*)d_out;

    // Idempotent, capture-safe (not a stream op); no static guards per harness rules.
    cudaFuncSetAttribute(xp_gemm, cudaFuncAttributeMaxDynamicSharedMemorySize, SMEM_TOTAL);

    xp_gemm<<<Mtot / MT, 256, SMEM_TOTAL>>>(x, Wih, bih, bhh);
    rnn_tail<<<Bb, 128>>>(Whh, Wfc, bfc, out);
}

// round 5
// speedup vs baseline: 1.3773x; 1.3773x over previous
#include <cuda_runtime.h>
#include <cuda_fp16.h>
#include <cstdint>

#define DEV_INLINE __device__ __forceinline__

// Problem shape (fixed)
static constexpr int Bb = 256, Tt = 256, Ii = 2048, Hh = 128;
static constexpr int Mtot = Bb * Tt;      // 65536 rows of xp
static constexpr int MT   = 256;          // M rows per CTA
static constexpr int NT   = 128;          // N (= full H)
static constexpr int KT   = 32;           // K floats per tile
static constexpr int NKT  = Ii / KT;      // 64 K tiles
// fp16 smem tiles: 64 bytes per row (32 fp16), SW64-style swizzle
static constexpr int A_BYTES = MT * 64;           // 16 KB
static constexpr int B_BYTES = NT * 64;           // 8 KB
static constexpr int STAGE_BYTES = A_BYTES + B_BYTES;   // 24 KB
static constexpr int STAGES = 4;
static constexpr int SMEM_TOTAL = STAGES * STAGE_BYTES + 1024;

// Scratch: xp[m][h] (32 MB) written by GEMM, read by recurrence
__device__ float g_xp[(size_t)Mtot * Hh];

// ---------------- helpers ----------------
DEV_INLINE uint32_t smem_u32(const void* p) {
    uint32_t a;
    asm("{ .reg .u64 t; cvta.to.shared.u64 t, %1; cvt.u32.u64 %0, t; }" : "=r"(a) : "l"(p));
    return a;
}
DEV_INLINE void ldsm_x4(uint32_t& r0, uint32_t& r1, uint32_t& r2, uint32_t& r3, uint32_t a) {
    asm volatile("ldmatrix.sync.aligned.m8n8.x4.shared.b16 {%0,%1,%2,%3}, [%4];"
                 : "=r"(r0), "=r"(r1), "=r"(r2), "=r"(r3) : "r"(a));
}
DEV_INLINE void ldsm_x2(uint32_t& r0, uint32_t& r1, uint32_t a) {
    asm volatile("ldmatrix.sync.aligned.m8n8.x2.shared.b16 {%0,%1}, [%2];"
                 : "=r"(r0), "=r"(r1) : "r"(a));
}
DEV_INLINE void mma_f16(float* c, uint32_t a0, uint32_t a1, uint32_t a2, uint32_t a3,
                        uint32_t b0, uint32_t b1) {
    asm volatile("mma.sync.aligned.m16n8k16.row.col.f32.f16.f16.f32 "
                 "{%0,%1,%2,%3}, {%4,%5,%6,%7}, {%8,%9}, {%0,%1,%2,%3};"
                 : "+f"(c[0]), "+f"(c[1]), "+f"(c[2]), "+f"(c[3])
                 : "r"(a0), "r"(a1), "r"(a2), "r"(a3), "r"(b0), "r"(b1));
}
DEV_INLINE uint32_t f2h2(float a, float b) {
    __half2 h = __floats2half2_rn(a, b);
    return *reinterpret_cast<uint32_t*>(&h);
}
DEV_INLINE void sts128(uint32_t addr, uint32_t r0, uint32_t r1, uint32_t r2, uint32_t r3) {
    asm volatile("st.shared.v4.b32 [%0], {%1,%2,%3,%4};"
                 :: "r"(addr), "r"(r0), "r"(r1), "r"(r2), "r"(r3));
}
// Blackwell packed fp32x2 math (PTX ISA 8.6, sm_100+)
DEV_INLINE uint64_t fma2(uint64_t a, uint64_t b, uint64_t c) {
    uint64_t d;
    asm("fma.rn.f32x2 %0, %1, %2, %3;" : "=l"(d) : "l"(a), "l"(b), "l"(c));
    return d;
}
DEV_INLINE uint64_t add2(uint64_t a, uint64_t b) {
    uint64_t d;
    asm("add.rn.f32x2 %0, %1, %2;" : "=l"(d) : "l"(a), "l"(b));
    return d;
}

// ---------------- Kernel A: xp = x @ W_ih^T + (b_ih+b_hh), fp16 m16n8k16 ----------------
// CTA: 256x128 tile, 8 warps (4 M x 2 N), warp tile 64x64. fp32->fp16 conversion happens
// once per element in the LDG->STS path; mainloop is pure ldmatrix + HMMA.16816.
__global__ void __launch_bounds__(256, 1) xp_gemm(
    const float* __restrict__ x, const float* __restrict__ Wih,
    const float* __restrict__ bih, const float* __restrict__ bhh)
{
    extern __shared__ char dsm[];
    __shared__ float s_bias[NT];

    const int tid = threadIdx.x;
    const int wid = tid >> 5, lane = tid & 31;
    const int warp_m = wid >> 1, warp_n = wid & 1;        // 4 x 2
    const int g = lane >> 2, tig = lane & 3;
    const uint32_t base = (smem_u32(dsm) + 1023u) & ~1023u;
    const int m_base = blockIdx.x * MT;

    if (tid < NT) s_bias[tid] = bih[tid] + bhh[tid];

    // granule mapping: each thread owns 6 granules (16B fp16 = 8 consecutive k-floats)
    // A: g = i*256 + tid, i<4 : row = g>>2 (0..255), chunk = g&3
    // B: g = i*256 + tid, i<2 : row = g>>2 (0..127), chunk = g&3
    const int gr = tid >> 2, gc = tid & 3;

    float4 la[4][2], lb[2][2];      // reg staging for one stage

    auto ldg_stage = [&](int kc) {
        const float* pA = x + (size_t)(m_base + gr) * Ii + kc * KT + gc * 8;
        #pragma unroll
        for (int i = 0; i < 4; i++) {
            la[i][0] = *reinterpret_cast<const float4*>(pA + (size_t)i * 64 * Ii);
            la[i][1] = *reinterpret_cast<const float4*>(pA + (size_t)i * 64 * Ii + 4);
        }
        const float* pB = Wih + (size_t)gr * Ii + kc * KT + gc * 8;
        #pragma unroll
        for (int i = 0; i < 2; i++) {
            lb[i][0] = *reinterpret_cast<const float4*>(pB + (size_t)i * 64 * Ii);
            lb[i][1] = *reinterpret_cast<const float4*>(pB + (size_t)i * 64 * Ii + 4);
        }
    };
    auto sts_stage = [&](int s) {
        const uint32_t sA = base + s * STAGE_BYTES;
        const uint32_t sB = sA + A_BYTES;
        #pragma unroll
        for (int i = 0; i < 4; i++) {
            int row = gr + i * 64;
            uint32_t off = row * 64 + ((gc ^ ((row >> 1) & 3)) << 4);
            sts128(sA + off, f2h2(la[i][0].x, la[i][0].y), f2h2(la[i][0].z, la[i][0].w),
                             f2h2(la[i][1].x, la[i][1].y), f2h2(la[i][1].z, la[i][1].w));
        }
        #pragma unroll
        for (int i = 0; i < 2; i++) {
            int row = gr + i * 64;
            uint32_t off = row * 64 + ((gc ^ ((row >> 1) & 3)) << 4);
            sts128(sB + off, f2h2(lb[i][0].x, lb[i][0].y), f2h2(lb[i][0].z, lb[i][0].w),
                             f2h2(lb[i][1].x, lb[i][1].y), f2h2(lb[i][1].z, lb[i][1].w));
        }
    };

    // ldmatrix per-lane address components
    const int am = lane >> 3, aj = lane & 7;
    const int a_row  = warp_m * 64 + (am & 1) * 8 + aj;       // + ma*16 (swizzle-invariant)
    const int a_csel = am >> 1;
    const int bm = (lane & 15) >> 3, bj = lane & 7;
    const int b_row  = warp_n * 64 + bj;                      // + na*8 (swizzle-invariant)
    uint32_t aswz[2], bswz[2];
    #pragma unroll
    for (int s2 = 0; s2 < 2; s2++) {
        aswz[s2] = (uint32_t)(((s2 * 2 + a_csel) ^ ((a_row >> 1) & 3)) << 4);
        bswz[s2] = (uint32_t)(((s2 * 2 + bm)     ^ ((b_row >> 1) & 3)) << 4);
    }

    float acc[4][8][4];
    #pragma unroll
    for (int ma = 0; ma < 4; ma++)
        #pragma unroll
        for (int na = 0; na < 8; na++)
            #pragma unroll
            for (int q = 0; q < 4; q++) acc[ma][na][q] = 0.0f;

    // prologue: stages 0,1 in smem; regs hold stage 2
    ldg_stage(0); sts_stage(0);
    ldg_stage(1); sts_stage(1);
    ldg_stage(2);

    for (int kc = 0; kc < NKT; kc++) {
        if (kc + 2 < NKT) sts_stage((kc + 2) & 3);   // regs -> smem (data loaded last iter)
        if (kc + 3 < NKT) ldg_stage(kc + 3);          // refill regs; latency hidden by MMA
        __syncthreads();                              // stage kc visible to all warps

        const uint32_t sA = base + (kc & 3) * STAGE_BYTES;
        const uint32_t sB = sA + A_BYTES;
        const uint32_t aA = sA + a_row * 64;
        const uint32_t aB = sB + b_row * 64;

        #pragma unroll
        for (int st = 0; st < 2; st++) {              // two k16 steps per tile
            uint32_t a[4][4], b[8][2];
            #pragma unroll
            for (int ma = 0; ma < 4; ma++)
                ldsm_x4(a[ma][0], a[ma][1], a[ma][2], a[ma][3], aA + ma * 1024 + aswz[st]);
            #pragma unroll
            for (int na = 0; na < 8; na++)
                ldsm_x2(b[na][0], b[na][1], aB + na * 512 + bswz[st]);
            #pragma unroll
            for (int ma = 0; ma < 4; ma++)
                #pragma unroll
                for (int na = 0; na < 8; na++)
                    mma_f16(acc[ma][na], a[ma][0], a[ma][1], a[ma][2], a[ma][3],
                            b[na][0], b[na][1]);
        }
        __syncthreads();   // all warps done reading stage kc before it is overwritten (kc+2)
    }

    // epilogue: + bias -> g_xp (float2 stores, C-fragment layout)
    const int n0 = warp_n * 64 + tig * 2;
    float2 biasv[8];
    #pragma unroll
    for (int na = 0; na < 8; na++) {
        biasv[na].x = s_bias[n0 + na * 8];
        biasv[na].y = s_bias[n0 + na * 8 + 1];
    }
    const int r0 = m_base + warp_m * 64 + g;
    #pragma unroll
    for (int ma = 0; ma < 4; ma++) {
        float* p0 = g_xp + (size_t)(r0 + ma * 16) * Hh;
        float* p1 = p0 + (size_t)8 * Hh;
        #pragma unroll
        for (int na = 0; na < 8; na++) {
            int col = n0 + na * 8;
            float2 v0 = make_float2(acc[ma][na][0] + biasv[na].x, acc[ma][na][1] + biasv[na].y);
            float2 v1 = make_float2(acc[ma][na][2] + biasv[na].x, acc[ma][na][3] + biasv[na].y);
            *reinterpret_cast<float2*>(p0 + col) = v0;
            *reinterpret_cast<float2*>(p1 + col) = v1;
        }
    }
}

// ---------------- Kernel B: 256 sequential tanh-RNN steps + final FC ----------------
// One CTA per batch row; W_hh row j register-resident (as f32x2 pairs) in thread j.
// Packed fma.rn.f32x2 halves FMA issue count and dependency depth; xp prefetched
// 2 steps ahead to cover L2 latency.
__global__ void __launch_bounds__(128, 2) rnn_tail(
    const float* __restrict__ Whh, const float* __restrict__ Wfc,
    const float* __restrict__ bfc, float* __restrict__ out)
{
    __shared__ __align__(16) float hbuf[2][128];
    __shared__ float red[4];
    const int j = threadIdx.x;
    const int b = blockIdx.x;

    uint64_t w64[64];                       // Whh row j as 64 packed fp32 pairs
    #pragma unroll
    for (int i = 0; i < 32; i++) {
        ulonglong2 v = *reinterpret_cast<const ulonglong2*>(Whh + (size_t)j * Hh + i * 4);
        w64[2 * i]     = v.x;
        w64[2 * i + 1] = v.y;
    }
    const float wfc = Wfc[j];
    hbuf[0][j] = 0.0f;
    __syncthreads();

    const float* xrow = g_xp + ((size_t)b * Tt) * Hh + j;
    float xv = xrow[0];
    float x1 = xrow[Hh];

    for (int t = 0; t < Tt; t++) {
        float x2 = (t + 2 < Tt) ? xrow[(size_t)(t + 2) * Hh] : 0.0f;   // distance-2 prefetch
        const uint64_t* hb = reinterpret_cast<const uint64_t*>(hbuf[t & 1]);
        uint64_t c0 = (uint64_t)__float_as_uint(xv);    // lo = xv, hi = 0
        uint64_t c1 = 0, c2 = 0, c3 = 0;
        #pragma unroll
        for (int k = 0; k < 16; k++) {
            ulonglong2 p0 = *reinterpret_cast<const ulonglong2*>(hb + 4 * k);
            ulonglong2 p1 = *reinterpret_cast<const ulonglong2*>(hb + 4 * k + 2);
            c0 = fma2(p0.x, w64[4 * k + 0], c0);
            c1 = fma2(p0.y, w64[4 * k + 1], c1);
            c2 = fma2(p1.x, w64[4 * k + 2], c2);
            c3 = fma2(p1.y, w64[4 * k + 3], c3);
        }
        uint64_t s = add2(add2(c0, c1), add2(c2, c3));
        float a = __uint_as_float((uint32_t)s) + __uint_as_float((uint32_t)(s >> 32));
        float u  = __expf(2.0f * a);
        float hn = 1.0f - __fdividef(2.0f, u + 1.0f);
        hbuf[(t + 1) & 1][j] = hn;
        xv = x1; x1 = x2;
        __syncthreads();
    }

    float v = wfc * hbuf[0][j];
    #pragma unroll
    for (int o = 16; o > 0; o >>= 1) v += __shfl_down_sync(0xFFFFFFFFu, v, o);
    if ((j & 31) == 0) red[j >> 5] = v;
    __syncthreads();
    if (j == 0) out[b] = red[0] + red[1] + red[2] + red[3] + bfc[0];
}

// ---------------- launch ----------------
extern "C" void kernel_launch(void* const* d_in, const int* in_sizes, int n_in,
                              void* d_out, int out_size)
{
    const float* x   = (const float*)d_in[0];
    const float* Wih = (const float*)d_in[1];
    const float* Whh = (const float*)d_in[2];
    const float* bih = (const float*)d_in[3];
    const float* bhh = (const float*)d_in[4];
    const float* Wfc = (const float*)d_in[5];
    const float* bfc = (const float*)d_in[6];
    float* out = (float*)d_out;

    cudaFuncSetAttribute(xp_gemm, cudaFuncAttributeMaxDynamicSharedMemorySize, SMEM_TOTAL);

    xp_gemm<<<Mtot / MT, 256, SMEM_TOTAL>>>(x, Wih, bih, bhh);
    rnn_tail<<<Bb, 128>>>(Whh, Wfc, bfc, out);
}